// round 8
// baseline (speedup 1.0000x reference)
#include <cuda_runtime.h>
#include <cuda_fp16.h>
#include <cstdint>
#include <math.h>

// ---------------- problem constants ----------------
constexpr int SEQ = 2048;
constexpr int NH  = 32;
constexpr int NKV = 8;
constexpr int HD  = 128;
// SCALE * log2(e): scores computed in log2 domain -> ex2
constexpr float SCALE2 = 0.08838834764831845f * 1.4426950408889634f;

constexpr int BM = 128;   // queries per CTA (4 pairs x 32 rows)
constexpr int BN = 64;    // keys per tile

// ---------------- device scratch: fp16 K, V ----------------
__device__ __half g_kh[SEQ * NKV * HD];
__device__ __half g_vh[SEQ * NKV * HD];

// ---------------- helpers ----------------
__device__ __forceinline__ uint32_t smem_u32(const void* p) {
    uint32_t a;
    asm("{ .reg .u64 t; cvta.to.shared.u64 t, %1; cvt.u32.u64 %0, t; }" : "=r"(a) : "l"(p));
    return a;
}
__device__ __forceinline__ uint32_t packh(__half a, __half b) {
    __half2 t = __halves2half2(a, b);
    return *reinterpret_cast<uint32_t*>(&t);
}
__device__ __forceinline__ float ex2(float x) {
    float y;
    asm("ex2.approx.ftz.f32 %0, %1;" : "=f"(y) : "f"(x));
    return y;
}
// xor swizzle for 256B rows (K/V/Q layout)
__device__ __forceinline__ uint32_t sw(int r, int c16) {
    return (uint32_t)(r * 256 + (((c16) ^ (r & 7)) << 4));
}

#define CP_ASYNC16(dst, src) \
    asm volatile("cp.async.cg.shared.global [%0], [%1], 16;" :: "r"(dst), "l"(src))
#define CP_COMMIT() asm volatile("cp.async.commit_group;" ::: "memory")
#define CP_WAIT0()  asm volatile("cp.async.wait_group 0;" ::: "memory")

__device__ __forceinline__ void ldsm4(uint32_t* r, uint32_t addr) {
    asm volatile("ldmatrix.sync.aligned.m8n8.x4.shared.b16 {%0,%1,%2,%3}, [%4];"
                 : "=r"(r[0]), "=r"(r[1]), "=r"(r[2]), "=r"(r[3]) : "r"(addr));
}
__device__ __forceinline__ void ldsm4t(uint32_t* r, uint32_t addr) {
    asm volatile("ldmatrix.sync.aligned.m8n8.x4.trans.shared.b16 {%0,%1,%2,%3}, [%4];"
                 : "=r"(r[0]), "=r"(r[1]), "=r"(r[2]), "=r"(r[3]) : "r"(addr));
}
__device__ __forceinline__ void sts32(uint32_t addr, uint32_t v) {
    asm volatile("st.shared.b32 [%0], %1;" :: "r"(addr), "r"(v) : "memory");
}
__device__ __forceinline__ void mma16816(float* d, const uint32_t* a, const uint32_t* b) {
    asm volatile("mma.sync.aligned.m16n8k16.row.col.f32.f16.f16.f32 "
                 "{%0,%1,%2,%3}, {%4,%5,%6,%7}, {%8,%9}, {%0,%1,%2,%3};"
                 : "+f"(d[0]), "+f"(d[1]), "+f"(d[2]), "+f"(d[3])
                 : "r"(a[0]), "r"(a[1]), "r"(a[2]), "r"(a[3]), "r"(b[0]), "r"(b[1]));
}

// ---------------- prep: K,V fp32 -> fp16 ----------------
__global__ void prep_h(const float* __restrict__ gk, const float* __restrict__ gv) {
    size_t idx = (size_t)blockIdx.x * blockDim.x + threadIdx.x;
    size_t base = idx * 8;
    uint32_t h[4];
    #pragma unroll
    for (int i = 0; i < 4; ++i)
        h[i] = packh(__float2half_rn(gk[base + 2 * i]), __float2half_rn(gk[base + 2 * i + 1]));
    *reinterpret_cast<uint4*>(g_kh + base) = make_uint4(h[0], h[1], h[2], h[3]);
    #pragma unroll
    for (int i = 0; i < 4; ++i)
        h[i] = packh(__float2half_rn(gv[base + 2 * i]), __float2half_rn(gv[base + 2 * i + 1]));
    *reinterpret_cast<uint4*>(g_vh + base) = make_uint4(h[0], h[1], h[2], h[3]);
}

// ---------------- smem layout ----------------
// [0, 32768)      : Q initial staging (128 rows x 256B, swizzled) -- dead after hoist
//   [0, 16384)    : P staging (128 rows x 128B, swizzled)  [reuses Q region in main loop]
//   [16384, 17408): lsums: 128 rows x 2 sides x float       [used in epilogue only]
// [32768, 98304)  : 2 stages x [K 16KB | V 16KB]
constexpr int P_OFF   = 0;
constexpr int LS_OFF  = 16384;
constexpr int Q_OFF   = 0;
constexpr int STG_OFF = 32768;
constexpr int STG_SZ  = 32768;
constexpr int SMEM_TOTAL = STG_OFF + 2 * STG_SZ;   // 98304 B

__device__ __forceinline__ void load_kv(uint32_t sb_stage, int kbase, int kvh, int tid) {
    #pragma unroll
    for (int i = 0; i < 4; ++i) {
        int q = tid + i * 256;           // 0..1023 chunk within each buffer
        int r = q >> 4, c16 = q & 15;
        size_t go = (size_t)(kbase + r) * (NKV * HD) + kvh * HD + c16 * 8;
        uint32_t so = sw(r, c16);
        CP_ASYNC16(sb_stage +         so, g_kh + go);
        CP_ASYNC16(sb_stage + 16384 + so, g_vh + go);
    }
}

// ---------------- main kernel ----------------
__global__ __launch_bounds__(256, 1)
void fa_mma(const float* __restrict__ gq, float* __restrict__ gout)
{
    extern __shared__ char smem[];
    const uint32_t sb = smem_u32(smem);
    const int tid  = threadIdx.x;
    const int warp = tid >> 5;
    const int lane = tid & 31;
    const int pair = warp >> 1;      // 0..3 : owns rows 32*pair .. +31
    const int side = warp & 1;       // 0/1  : S keys 32s..+31 ; PV dims 64s..+63

    const int head   = blockIdx.x;
    const int qi     = (int)(gridDim.y - 1) - (int)blockIdx.y;   // heavy first
    const int kvh    = head >> 2;
    const int qbase  = qi * BM;
    const int ntiles = 2 * qi + 2;

    // prefetch stage 0 K/V
    load_kv(sb + STG_OFF, 0, kvh, tid);
    CP_COMMIT();

    // ---- Q: load fp32, scale (incl log2e), fp16, store swizzled (256B rows) ----
    #pragma unroll
    for (int i = 0; i < 8; ++i) {
        int idx = tid + i * 256;
        int r = idx >> 4, c16 = idx & 15;
        const float* src = gq + (size_t)(qbase + r) * (NH * HD) + head * HD + c16 * 8;
        uint32_t h[4];
        #pragma unroll
        for (int e = 0; e < 4; ++e)
            h[e] = packh(__float2half_rn(src[2 * e] * SCALE2),
                         __float2half_rn(src[2 * e + 1] * SCALE2));
        *reinterpret_cast<uint4*>(smem + Q_OFF + sw(r, c16)) = make_uint4(h[0], h[1], h[2], h[3]);
    }
    __syncthreads();

    // ---- hoist Q fragments: rows 32*pair..+31 as two m16 blocks ----
    uint32_t qh[8][2][4];
    #pragma unroll
    for (int ks = 0; ks < 8; ++ks)
        #pragma unroll
        for (int rb = 0; rb < 2; ++rb) {
            int prow = pair * 32 + rb * 16 + (lane & 15);
            uint32_t aoff = (uint32_t)prow * 256 +
                            ((((uint32_t)(2 * ks) + (uint32_t)(lane >> 4)) ^ (uint32_t)(lane & 7)) << 4);
            ldsm4(qh[ks][rb], sb + Q_OFF + aoff);
        }

    // per-lane constants
    const uint32_t kRow8 = (uint32_t)((lane & 7) * 256);
    const uint32_t kHalf = (uint32_t)((lane >> 3) & 1);
    const uint32_t kJplus = (uint32_t)(lane >> 4);
    const uint32_t kXor  = (uint32_t)(lane & 7);

    const int pr_min = qbase + 32 * pair;        // smallest row of this pair
    const int pr_max = pr_min + 31;              // largest row of this pair

    float oacc[2][8][4];
    #pragma unroll
    for (int rb = 0; rb < 2; ++rb)
        #pragma unroll
        for (int jp = 0; jp < 8; ++jp)
            #pragma unroll
            for (int e = 0; e < 4; ++e) oacc[rb][jp][e] = 0.0f;
    float lsum[2][2] = {{0.f, 0.f}, {0.f, 0.f}};

    for (int t = 0; t < ntiles; ++t) {
        const int kbase = t * BN;
        const uint32_t stgK = sb + STG_OFF + (uint32_t)(t & 1) * STG_SZ;
        const uint32_t stgV = stgK + 16384;

        CP_WAIT0();
        __syncthreads();   // [A] stage t ready; prev tile's P/V reads complete

        if (t + 1 < ntiles) {
            load_kv(sb + STG_OFF + (uint32_t)((t + 1) & 1) * STG_SZ,
                    (t + 1) * BN, kvh, tid);
            CP_COMMIT();
        }

        const bool pair_active = (kbase <= pr_max);
        const int  cb = kbase + 32 * side;             // this warp's first S key
        const bool s_active = pair_active && (cb <= pr_max);

        if (s_active) {
            // ---- S: 32 rows x 32 keys, 8 indep chains ----
            float sacc[2][4][4];
            #pragma unroll
            for (int rb = 0; rb < 2; ++rb)
                #pragma unroll
                for (int jj = 0; jj < 4; ++jj)
                    #pragma unroll
                    for (int e = 0; e < 4; ++e) sacc[rb][jj][e] = 0.0f;

            const uint32_t kc0 = stgK + (uint32_t)(4 * side + kJplus) * 2048 + kRow8;
            const uint32_t kc1 = kc0 + 2 * 2048;
            #pragma unroll
            for (int ks = 0; ks < 8; ++ks) {
                uint32_t kba[4], kbb[4];
                uint32_t koff = (((uint32_t)(2 * ks) + kHalf) ^ kXor) << 4;
                ldsm4(kba, kc0 + koff);
                ldsm4(kbb, kc1 + koff);
                #pragma unroll
                for (int rb = 0; rb < 2; ++rb) {
                    mma16816(sacc[rb][0], qh[ks][rb], kba);
                    mma16816(sacc[rb][1], qh[ks][rb], kba + 2);
                    mma16816(sacc[rb][2], qh[ks][rb], kbb);
                    mma16816(sacc[rb][3], qh[ks][rb], kbb + 2);
                }
            }

            // ---- softmax + write P (fp16) to staging ----
            const bool full = (cb + 31 <= pr_min);
            #pragma unroll
            for (int rb = 0; rb < 2; ++rb) {
                const int r0 = pr_min + 16 * rb + (lane >> 2);
                const int r1 = r0 + 8;
                const int prow = 32 * pair + 16 * rb + (lane >> 2);
                #pragma unroll
                for (int jj = 0; jj < 4; ++jj) {
                    float p0, p1, p2, p3;
                    if (full) {
                        p0 = ex2(sacc[rb][jj][0]);
                        p1 = ex2(sacc[rb][jj][1]);
                        p2 = ex2(sacc[rb][jj][2]);
                        p3 = ex2(sacc[rb][jj][3]);
                    } else {
                        int col = cb + 8 * jj + 2 * (lane & 3);
                        p0 = (col     <= r0) ? ex2(sacc[rb][jj][0]) : 0.0f;
                        p1 = (col + 1 <= r0) ? ex2(sacc[rb][jj][1]) : 0.0f;
                        p2 = (col     <= r1) ? ex2(sacc[rb][jj][2]) : 0.0f;
                        p3 = (col + 1 <= r1) ? ex2(sacc[rb][jj][3]) : 0.0f;
                    }
                    lsum[rb][0] += p0 + p1;
                    lsum[rb][1] += p2 + p3;
                    // P staging: row-major 128 rows x 128B, swizzled 16B chunks
                    uint32_t c16 = (uint32_t)(4 * side + jj);
                    uint32_t a0 = sb + P_OFF + (uint32_t)prow * 128 +
                                  ((c16 ^ (uint32_t)(prow & 7)) << 4) + (uint32_t)(lane & 3) * 4;
                    sts32(a0,            packh(__float2half_rn(p0), __float2half_rn(p1)));
                    sts32(a0 + 8 * 128,  packh(__float2half_rn(p2), __float2half_rn(p3)));
                }
            }
        }

        __syncthreads();   // [B] P staging complete

        if (pair_active) {
            // ---- PV: O(32 rows x 64 dims[side]) += P(32 x nk) * V(nk x 64) ----
            const int nkc = (kbase + 32 <= pr_max) ? 4 : 2;   // k16 chunks of keys
            for (int kc = 0; kc < nkc; ++kc) {
                uint32_t af[2][4];
                #pragma unroll
                for (int rb = 0; rb < 2; ++rb) {
                    int prow = 32 * pair + 16 * rb + (lane & 15);
                    uint32_t aaddr = sb + P_OFF + (uint32_t)prow * 128 +
                        ((((uint32_t)(2 * kc) + (uint32_t)(lane >> 4)) ^ (uint32_t)(prow & 7)) << 4);
                    ldsm4(af[rb], aaddr);
                }
                #pragma unroll
                for (int jpp = 0; jpp < 4; ++jpp) {
                    uint32_t vb[4];
                    uint32_t vrow = (uint32_t)(16 * kc) + (uint32_t)(lane & 15);
                    uint32_t vaddr = stgV + vrow * 256 +
                        ((((uint32_t)(8 * side + 2 * jpp) + (uint32_t)(lane >> 4)) ^ (uint32_t)(lane & 7)) << 4);
                    ldsm4t(vb, vaddr);
                    mma16816(oacc[0][2 * jpp],     af[0], vb);
                    mma16816(oacc[0][2 * jpp + 1], af[0], vb + 2);
                    mma16816(oacc[1][2 * jpp],     af[1], vb);
                    mma16816(oacc[1][2 * jpp + 1], af[1], vb + 2);
                }
            }
        }
    }

    // ---- epilogue: combine l across quad + pair sides, normalize, store ----
    #pragma unroll
    for (int rb = 0; rb < 2; ++rb)
        #pragma unroll
        for (int h = 0; h < 2; ++h) {
            lsum[rb][h] += __shfl_xor_sync(0xffffffffu, lsum[rb][h], 1);
            lsum[rb][h] += __shfl_xor_sync(0xffffffffu, lsum[rb][h], 2);
        }
    float* ls = reinterpret_cast<float*>(smem + LS_OFF);
    if ((lane & 3) == 0) {
        #pragma unroll
        for (int rb = 0; rb < 2; ++rb)
            #pragma unroll
            for (int h = 0; h < 2; ++h) {
                int rl = 32 * pair + 16 * rb + (lane >> 2) + 8 * h;
                ls[rl * 2 + side] = lsum[rb][h];
            }
    }
    __syncthreads();

    #pragma unroll
    for (int rb = 0; rb < 2; ++rb) {
        const int rl0 = 32 * pair + 16 * rb + (lane >> 2);
        const int rl1 = rl0 + 8;
        const float inv0 = 1.0f / (ls[rl0 * 2] + ls[rl0 * 2 + 1]);
        const float inv1 = 1.0f / (ls[rl1 * 2] + ls[rl1 * 2 + 1]);
        float* o0 = gout + (size_t)(qbase + rl0) * (NH * HD) + head * HD + 64 * side + 2 * (lane & 3);
        float* o1 = gout + (size_t)(qbase + rl1) * (NH * HD) + head * HD + 64 * side + 2 * (lane & 3);
        #pragma unroll
        for (int jp = 0; jp < 8; ++jp) {
            *reinterpret_cast<float2*>(o0 + 8 * jp) =
                make_float2(oacc[rb][jp][0] * inv0, oacc[rb][jp][1] * inv0);
            *reinterpret_cast<float2*>(o1 + 8 * jp) =
                make_float2(oacc[rb][jp][2] * inv1, oacc[rb][jp][3] * inv1);
        }
    }
}

// ---------------- launch ----------------
extern "C" void kernel_launch(void* const* d_in, const int* in_sizes, int n_in,
                              void* d_out, int out_size)
{
    const float* q = (const float*)d_in[0];
    const float* k = (const float*)d_in[1];
    const float* v = (const float*)d_in[2];
    float* out = (float*)d_out;

    prep_h<<<(SEQ * NKV * HD / 8 + 255) / 256, 256>>>(k, v);

    cudaFuncSetAttribute(fa_mma, cudaFuncAttributeMaxDynamicSharedMemorySize, SMEM_TOTAL);
    fa_mma<<<dim3(NH, SEQ / BM), 256, SMEM_TOTAL>>>(q, out);
}

// round 9
// speedup vs baseline: 1.1101x; 1.1101x over previous
#include <cuda_runtime.h>
#include <cuda_fp16.h>
#include <cstdint>
#include <math.h>

// ---------------- problem constants ----------------
constexpr int SEQ = 2048;
constexpr int NH  = 32;
constexpr int NKV = 8;
constexpr int HD  = 128;
// SCALE * log2(e): scores computed directly in log2 domain -> ex2
constexpr float SCALE2 = 0.08838834764831845f * 1.4426950408889634f;

constexpr int BM = 128;   // queries per CTA (8 warps x 16 rows)
constexpr int BN = 64;    // keys per tile

// ---------------- device scratch: fp16 K, V ----------------
__device__ __half g_kh[SEQ * NKV * HD];
__device__ __half g_vh[SEQ * NKV * HD];

// ---------------- helpers ----------------
__device__ __forceinline__ uint32_t smem_u32(const void* p) {
    uint32_t a;
    asm("{ .reg .u64 t; cvta.to.shared.u64 t, %1; cvt.u32.u64 %0, t; }" : "=r"(a) : "l"(p));
    return a;
}
__device__ __forceinline__ uint32_t packh(__half a, __half b) {
    __half2 t = __halves2half2(a, b);
    return *reinterpret_cast<uint32_t*>(&t);
}
__device__ __forceinline__ float ex2(float x) {
    float y;
    asm("ex2.approx.ftz.f32 %0, %1;" : "=f"(y) : "f"(x));
    return y;
}
// xor swizzle: rows of 128 halves (256B = 16 chunks of 16B); conflict-free ldmatrix
__device__ __forceinline__ uint32_t sw(int r, int c16) {
    return (uint32_t)(r * 256 + (((c16) ^ (r & 7)) << 4));
}

#define CP_ASYNC16(dst, src) \
    asm volatile("cp.async.cg.shared.global [%0], [%1], 16;" :: "r"(dst), "l"(src))
#define CP_COMMIT() asm volatile("cp.async.commit_group;" ::: "memory")
#define CP_WAIT0()  asm volatile("cp.async.wait_group 0;" ::: "memory")
#define CP_WAIT1()  asm volatile("cp.async.wait_group 1;" ::: "memory")

__device__ __forceinline__ void ldsm4(uint32_t* r, uint32_t addr) {
    asm volatile("ldmatrix.sync.aligned.m8n8.x4.shared.b16 {%0,%1,%2,%3}, [%4];"
                 : "=r"(r[0]), "=r"(r[1]), "=r"(r[2]), "=r"(r[3]) : "r"(addr));
}
__device__ __forceinline__ void ldsm4t(uint32_t* r, uint32_t addr) {
    asm volatile("ldmatrix.sync.aligned.m8n8.x4.trans.shared.b16 {%0,%1,%2,%3}, [%4];"
                 : "=r"(r[0]), "=r"(r[1]), "=r"(r[2]), "=r"(r[3]) : "r"(addr));
}
__device__ __forceinline__ void mma16816(float* d, const uint32_t* a, const uint32_t* b) {
    asm volatile("mma.sync.aligned.m16n8k16.row.col.f32.f16.f16.f32 "
                 "{%0,%1,%2,%3}, {%4,%5,%6,%7}, {%8,%9}, {%0,%1,%2,%3};"
                 : "+f"(d[0]), "+f"(d[1]), "+f"(d[2]), "+f"(d[3])
                 : "r"(a[0]), "r"(a[1]), "r"(a[2]), "r"(a[3]), "r"(b[0]), "r"(b[1]));
}

// ---------------- prep: K,V fp32 -> fp16 ----------------
__global__ void prep_h(const float* __restrict__ gk, const float* __restrict__ gv) {
    size_t idx = (size_t)blockIdx.x * blockDim.x + threadIdx.x;   // chunk of 8 floats
    size_t base = idx * 8;
    uint32_t h[4];
    #pragma unroll
    for (int i = 0; i < 4; ++i)
        h[i] = packh(__float2half_rn(gk[base + 2 * i]), __float2half_rn(gk[base + 2 * i + 1]));
    *reinterpret_cast<uint4*>(g_kh + base) = make_uint4(h[0], h[1], h[2], h[3]);
    #pragma unroll
    for (int i = 0; i < 4; ++i)
        h[i] = packh(__float2half_rn(gv[base + 2 * i]), __float2half_rn(gv[base + 2 * i + 1]));
    *reinterpret_cast<uint4*>(g_vh + base) = make_uint4(h[0], h[1], h[2], h[3]);
}

// ---------------- smem layout ----------------
constexpr int QH_OFF  = 0;        // 128x128 half, swizzled, 32KB
constexpr int STG_OFF = 32768;    // 2 stages x [Kh|Vh] x 16KB
constexpr int STG_SZ  = 32768;
constexpr int SMEM_TOTAL = STG_OFF + 2 * STG_SZ;   // 98304 B

__device__ __forceinline__ void load_kv(uint32_t sb_stage, int kbase, int kvh, int tid) {
    #pragma unroll
    for (int i = 0; i < 4; ++i) {
        int q = tid + i * 256;           // 0..1023 chunk within each buffer
        int r = q >> 4, c16 = q & 15;
        size_t go = (size_t)(kbase + r) * (NKV * HD) + kvh * HD + c16 * 8;
        uint32_t so = sw(r, c16);
        CP_ASYNC16(sb_stage +         so, g_kh + go);
        CP_ASYNC16(sb_stage + 16384 + so, g_vh + go);
    }
}

// ---------------- main kernel ----------------
__global__ __launch_bounds__(256, 1)
void fa_mma(const float* __restrict__ gq, float* __restrict__ gout)
{
    extern __shared__ char smem[];
    const uint32_t sb = smem_u32(smem);
    const int tid  = threadIdx.x;
    const int warp = tid >> 5;
    const int lane = tid & 31;

    const int head   = blockIdx.x;
    const int qi     = (int)(gridDim.y - 1) - (int)blockIdx.y;   // heavy tiles first
    const int kvh    = head >> 2;
    const int qbase  = qi * BM;
    const int ntiles = 2 * qi + 2;

    // prefetch stage 0 K/V
    load_kv(sb + STG_OFF, 0, kvh, tid);
    CP_COMMIT();

    // ---- Q: load fp32, scale (incl log2e), fp16 convert, store swizzled ----
    #pragma unroll
    for (int i = 0; i < 8; ++i) {
        int idx = tid + i * 256;          // 2048 chunks
        int r = idx >> 4, c16 = idx & 15;
        const float* src = gq + (size_t)(qbase + r) * (NH * HD) + head * HD + c16 * 8;
        uint32_t h[4];
        #pragma unroll
        for (int e = 0; e < 4; ++e)
            h[e] = packh(__float2half_rn(src[2 * e] * SCALE2),
                         __float2half_rn(src[2 * e + 1] * SCALE2));
        *reinterpret_cast<uint4*>(smem + QH_OFF + sw(r, c16)) = make_uint4(h[0], h[1], h[2], h[3]);
    }
    __syncthreads();   // Q visible to all warps before fragment hoist

    // per-lane constants
    const uint32_t aRowByte = (uint32_t)((warp * 16 + (lane & 15)) * 256);
    const uint32_t aXor = (uint32_t)(lane & 7);
    const uint32_t aC0  = (uint32_t)(lane >> 4);
    const uint32_t kRow8  = (uint32_t)((lane & 7) * 256);
    const uint32_t kHalf  = (uint32_t)((lane >> 3) & 1);
    const uint32_t kJplus = (uint32_t)(lane >> 4);
    const uint32_t kXor   = (uint32_t)(lane & 7);
    const uint32_t vRow16 = (uint32_t)((lane & 15) * 256);
    const uint32_t vJplus = (uint32_t)(lane >> 4);
    const uint32_t vXor   = (uint32_t)(lane & 7);

    // ---- hoist Q fragments into registers; reused for all tiles ----
    uint32_t qh[8][4];
    #pragma unroll
    for (int ks = 0; ks < 8; ++ks) {
        uint32_t aoff = aRowByte + ((((uint32_t)(2 * ks) + aC0) ^ aXor) << 4);
        ldsm4(qh[ks], sb + QH_OFF + aoff);
    }

    const int row0 = qbase + warp * 16 + (lane >> 2);
    const int row1 = row0 + 8;
    const int wrow_min = qbase + warp * 16;        // smallest q row in this warp
    const int wrow_max = wrow_min + 15;            // largest q row in this warp

    float oacc[16][4];
    #pragma unroll
    for (int j = 0; j < 16; ++j)
        #pragma unroll
        for (int e = 0; e < 4; ++e) oacc[j][e] = 0.0f;
    float lsum0 = 0.0f, lsum1 = 0.0f;

    for (int t = 0; t < ntiles; ++t) {
        const int kbase = t * BN;
        const uint32_t stg = sb + STG_OFF + (uint32_t)(t & 1) * STG_SZ;

        if (t + 1 < ntiles) {
            load_kv(sb + STG_OFF + (uint32_t)((t + 1) & 1) * STG_SZ,
                    (t + 1) * BN, kvh, tid);
            CP_COMMIT();
            CP_WAIT1();
        } else {
            CP_WAIT0();
        }
        __syncthreads();

        const uint32_t stgKh = stg;
        const uint32_t stgVh = stg + 16384;

        if (kbase + BN - 1 <= wrow_min) {
            // ======== HOT PATH: fully unmasked tile ========
            // S for all 64 keys in one loop: 8 independent accumulator chains
            float sacc[8][4];
            #pragma unroll
            for (int jj = 0; jj < 8; ++jj)
                #pragma unroll
                for (int e = 0; e < 4; ++e) sacc[jj][e] = 0.0f;

            #pragma unroll
            for (int ks = 0; ks < 8; ++ks) {
                uint32_t koff = (((uint32_t)(2 * ks) + kHalf) ^ kXor) << 4;
                #pragma unroll
                for (int g = 0; g < 4; ++g) {   // 4 groups of 16 keys
                    uint32_t kb[4];
                    ldsm4(kb, stgKh + ((uint32_t)(2 * g) + kJplus) * 2048 + kRow8 + koff);
                    mma16816(sacc[2 * g],     qh[ks], kb);
                    mma16816(sacc[2 * g + 1], qh[ks], kb + 2);
                }
            }

            // softmax (no masking) + PV per 32-key half; exp of half 1 can
            // overlap PV MMAs of half 0 (independent register chains)
            #pragma unroll
            for (int c = 0; c < 2; ++c) {
                float p[4][4];
                #pragma unroll
                for (int jj = 0; jj < 4; ++jj)
                    #pragma unroll
                    for (int e = 0; e < 4; ++e) p[jj][e] = ex2(sacc[4 * c + jj][e]);
                #pragma unroll
                for (int jj = 0; jj < 4; ++jj) {
                    lsum0 += p[jj][0] + p[jj][1];
                    lsum1 += p[jj][2] + p[jj][3];
                }
                uint32_t af[2][4];
                #pragma unroll
                for (int kf = 0; kf < 2; ++kf) {
                    af[kf][0] = packh(__float2half_rn(p[2 * kf][0]),     __float2half_rn(p[2 * kf][1]));
                    af[kf][1] = packh(__float2half_rn(p[2 * kf][2]),     __float2half_rn(p[2 * kf][3]));
                    af[kf][2] = packh(__float2half_rn(p[2 * kf + 1][0]), __float2half_rn(p[2 * kf + 1][1]));
                    af[kf][3] = packh(__float2half_rn(p[2 * kf + 1][2]), __float2half_rn(p[2 * kf + 1][3]));
                }
                #pragma unroll
                for (int kf = 0; kf < 2; ++kf) {
                    const uint32_t vcb = stgVh + (uint32_t)(2 * c + kf) * 4096 + vRow16;
                    #pragma unroll
                    for (int jp = 0; jp < 8; ++jp) {
                        uint32_t vb[4];
                        ldsm4t(vb, vcb + ((((uint32_t)(2 * jp) + vJplus) ^ vXor) << 4));
                        mma16816(oacc[2 * jp],     af[kf], vb);
                        mma16816(oacc[2 * jp + 1], af[kf], vb + 2);
                    }
                }
            }
        } else if (kbase <= wrow_max) {
            // ======== DIAGONAL PATH: chunked with masking (<=2 tiles/warp) ====
            #pragma unroll
            for (int c = 0; c < 2; ++c) {
                const int cb = kbase + 32 * c;      // first key of chunk
                if (cb > wrow_max) break;           // chunk (and later) fully masked

                float sacc[4][4];
                #pragma unroll
                for (int jj = 0; jj < 4; ++jj)
                    #pragma unroll
                    for (int e = 0; e < 4; ++e) sacc[jj][e] = 0.0f;

                const uint32_t kc0 = stgKh + (uint32_t)(4 * c + kJplus) * 2048 + kRow8;
                const uint32_t kc1 = kc0 + 2 * 2048;
                #pragma unroll
                for (int ks = 0; ks < 8; ++ks) {
                    uint32_t kba[4], kbb[4];
                    uint32_t koff = (((uint32_t)(2 * ks) + kHalf) ^ kXor) << 4;
                    ldsm4(kba, kc0 + koff);
                    ldsm4(kbb, kc1 + koff);
                    mma16816(sacc[0], qh[ks], kba);
                    mma16816(sacc[1], qh[ks], kba + 2);
                    mma16816(sacc[2], qh[ks], kbb);
                    mma16816(sacc[3], qh[ks], kbb + 2);
                }

                float p[4][4];
                #pragma unroll
                for (int jj = 0; jj < 4; ++jj) {
                    int col = cb + 8 * jj + 2 * (lane & 3);
                    p[jj][0] = (col     <= row0) ? ex2(sacc[jj][0]) : 0.0f;
                    p[jj][1] = (col + 1 <= row0) ? ex2(sacc[jj][1]) : 0.0f;
                    p[jj][2] = (col     <= row1) ? ex2(sacc[jj][2]) : 0.0f;
                    p[jj][3] = (col + 1 <= row1) ? ex2(sacc[jj][3]) : 0.0f;
                }
                #pragma unroll
                for (int jj = 0; jj < 4; ++jj) {
                    lsum0 += p[jj][0] + p[jj][1];
                    lsum1 += p[jj][2] + p[jj][3];
                }
                uint32_t af[2][4];
                #pragma unroll
                for (int kf = 0; kf < 2; ++kf) {
                    af[kf][0] = packh(__float2half_rn(p[2 * kf][0]),     __float2half_rn(p[2 * kf][1]));
                    af[kf][1] = packh(__float2half_rn(p[2 * kf][2]),     __float2half_rn(p[2 * kf][3]));
                    af[kf][2] = packh(__float2half_rn(p[2 * kf + 1][0]), __float2half_rn(p[2 * kf + 1][1]));
                    af[kf][3] = packh(__float2half_rn(p[2 * kf + 1][2]), __float2half_rn(p[2 * kf + 1][3]));
                }
                #pragma unroll
                for (int kf = 0; kf < 2; ++kf) {
                    const uint32_t vcb = stgVh + (uint32_t)(2 * c + kf) * 4096 + vRow16;
                    #pragma unroll
                    for (int jp = 0; jp < 8; ++jp) {
                        uint32_t vb[4];
                        ldsm4t(vb, vcb + ((((uint32_t)(2 * jp) + vJplus) ^ vXor) << 4));
                        mma16816(oacc[2 * jp],     af[kf], vb);
                        mma16816(oacc[2 * jp + 1], af[kf], vb + 2);
                    }
                }
            }
        }
        __syncthreads();
    }

    // ---- epilogue: reduce l, normalize, store ----
    lsum0 += __shfl_xor_sync(0xffffffffu, lsum0, 1);
    lsum0 += __shfl_xor_sync(0xffffffffu, lsum0, 2);
    lsum1 += __shfl_xor_sync(0xffffffffu, lsum1, 1);
    lsum1 += __shfl_xor_sync(0xffffffffu, lsum1, 2);
    const float inv0 = 1.0f / lsum0;
    const float inv1 = 1.0f / lsum1;

    float* out0 = gout + (size_t)row0 * (NH * HD) + head * HD + 2 * (lane & 3);
    float* out1 = gout + (size_t)row1 * (NH * HD) + head * HD + 2 * (lane & 3);
    #pragma unroll
    for (int j = 0; j < 16; ++j) {
        float2 a = make_float2(oacc[j][0] * inv0, oacc[j][1] * inv0);
        float2 b = make_float2(oacc[j][2] * inv1, oacc[j][3] * inv1);
        *reinterpret_cast<float2*>(out0 + 8 * j) = a;
        *reinterpret_cast<float2*>(out1 + 8 * j) = b;
    }
}

// ---------------- launch ----------------
extern "C" void kernel_launch(void* const* d_in, const int* in_sizes, int n_in,
                              void* d_out, int out_size)
{
    const float* q = (const float*)d_in[0];
    const float* k = (const float*)d_in[1];
    const float* v = (const float*)d_in[2];
    float* out = (float*)d_out;

    prep_h<<<(SEQ * NKV * HD / 8 + 255) / 256, 256>>>(k, v);

    cudaFuncSetAttribute(fa_mma, cudaFuncAttributeMaxDynamicSharedMemorySize, SMEM_TOTAL);
    fa_mma<<<dim3(NH, SEQ / BM), 256, SMEM_TOTAL>>>(q, out);
}

// round 10
// speedup vs baseline: 1.1751x; 1.0586x over previous
#include <cuda_runtime.h>
#include <cuda_fp16.h>
#include <cstdint>
#include <math.h>

// ---------------- problem constants ----------------
constexpr int SEQ = 2048;
constexpr int NH  = 32;
constexpr int NKV = 8;
constexpr int HD  = 128;
// SCALE * log2(e): scores computed directly in log2 domain -> ex2
constexpr float SCALE2 = 0.08838834764831845f * 1.4426950408889634f;

constexpr int BM = 64;    // queries per CTA (4 warps x 16 rows)
constexpr int BN = 64;    // keys per tile
constexpr int NTHREADS = 128;

// ---------------- device scratch: fp16 K, V ----------------
__device__ __half g_kh[SEQ * NKV * HD];
__device__ __half g_vh[SEQ * NKV * HD];

// ---------------- helpers ----------------
__device__ __forceinline__ uint32_t smem_u32(const void* p) {
    uint32_t a;
    asm("{ .reg .u64 t; cvta.to.shared.u64 t, %1; cvt.u32.u64 %0, t; }" : "=r"(a) : "l"(p));
    return a;
}
__device__ __forceinline__ uint32_t packh(__half a, __half b) {
    __half2 t = __halves2half2(a, b);
    return *reinterpret_cast<uint32_t*>(&t);
}
__device__ __forceinline__ float ex2(float x) {
    float y;
    asm("ex2.approx.ftz.f32 %0, %1;" : "=f"(y) : "f"(x));
    return y;
}
// xor swizzle: rows of 128 halves (256B = 16 chunks of 16B); conflict-free ldmatrix
__device__ __forceinline__ uint32_t sw(int r, int c16) {
    return (uint32_t)(r * 256 + (((c16) ^ (r & 7)) << 4));
}

#define CP_ASYNC16(dst, src) \
    asm volatile("cp.async.cg.shared.global [%0], [%1], 16;" :: "r"(dst), "l"(src))
#define CP_COMMIT() asm volatile("cp.async.commit_group;" ::: "memory")
#define CP_WAIT0()  asm volatile("cp.async.wait_group 0;" ::: "memory")

__device__ __forceinline__ void ldsm4(uint32_t* r, uint32_t addr) {
    asm volatile("ldmatrix.sync.aligned.m8n8.x4.shared.b16 {%0,%1,%2,%3}, [%4];"
                 : "=r"(r[0]), "=r"(r[1]), "=r"(r[2]), "=r"(r[3]) : "r"(addr));
}
__device__ __forceinline__ void ldsm4t(uint32_t* r, uint32_t addr) {
    asm volatile("ldmatrix.sync.aligned.m8n8.x4.trans.shared.b16 {%0,%1,%2,%3}, [%4];"
                 : "=r"(r[0]), "=r"(r[1]), "=r"(r[2]), "=r"(r[3]) : "r"(addr));
}
__device__ __forceinline__ void mma16816(float* d, const uint32_t* a, const uint32_t* b) {
    asm volatile("mma.sync.aligned.m16n8k16.row.col.f32.f16.f16.f32 "
                 "{%0,%1,%2,%3}, {%4,%5,%6,%7}, {%8,%9}, {%0,%1,%2,%3};"
                 : "+f"(d[0]), "+f"(d[1]), "+f"(d[2]), "+f"(d[3])
                 : "r"(a[0]), "r"(a[1]), "r"(a[2]), "r"(a[3]), "r"(b[0]), "r"(b[1]));
}

// ---------------- prep: K,V fp32 -> fp16 ----------------
__global__ void prep_h(const float* __restrict__ gk, const float* __restrict__ gv) {
    size_t idx = (size_t)blockIdx.x * blockDim.x + threadIdx.x;   // chunk of 8 floats
    size_t base = idx * 8;
    uint32_t h[4];
    #pragma unroll
    for (int i = 0; i < 4; ++i)
        h[i] = packh(__float2half_rn(gk[base + 2 * i]), __float2half_rn(gk[base + 2 * i + 1]));
    *reinterpret_cast<uint4*>(g_kh + base) = make_uint4(h[0], h[1], h[2], h[3]);
    #pragma unroll
    for (int i = 0; i < 4; ++i)
        h[i] = packh(__float2half_rn(gv[base + 2 * i]), __float2half_rn(gv[base + 2 * i + 1]));
    *reinterpret_cast<uint4*>(g_vh + base) = make_uint4(h[0], h[1], h[2], h[3]);
}

// ---------------- smem layout (per CTA) ----------------
constexpr int QH_OFF  = 0;        // 64x128 half, swizzled, 16KB
constexpr int STG_OFF = 16384;    // 2 stages x [Kh 16KB | Vh 16KB]
constexpr int STG_SZ  = 32768;
constexpr int SMEM_TOTAL = STG_OFF + 2 * STG_SZ;   // 81920 B -> 2 CTAs/SM

__device__ __forceinline__ void load_kv(uint32_t sb_stage, int kbase, int kvh, int tid) {
    #pragma unroll
    for (int i = 0; i < 8; ++i) {
        int q = tid + i * NTHREADS;      // 0..1023 chunk within each buffer
        int r = q >> 4, c16 = q & 15;
        size_t go = (size_t)(kbase + r) * (NKV * HD) + kvh * HD + c16 * 8;
        uint32_t so = sw(r, c16);
        CP_ASYNC16(sb_stage +         so, g_kh + go);
        CP_ASYNC16(sb_stage + 16384 + so, g_vh + go);
    }
}

// ---------------- main kernel ----------------
__global__ __launch_bounds__(NTHREADS, 2)
void fa_mma(const float* __restrict__ gq, float* __restrict__ gout)
{
    extern __shared__ char smem[];
    const uint32_t sb = smem_u32(smem);
    const int tid  = threadIdx.x;
    const int warp = tid >> 5;
    const int lane = tid & 31;

    const int head   = blockIdx.x;
    const int qi     = (int)(gridDim.y - 1) - (int)blockIdx.y;   // heavy tiles first
    const int kvh    = head >> 2;
    const int qbase  = qi * BM;
    const int ntiles = qi + 1;

    // prefetch stage 0 K/V
    load_kv(sb + STG_OFF, 0, kvh, tid);
    CP_COMMIT();

    // ---- Q: load fp32, scale (incl log2e), fp16 convert, store swizzled ----
    #pragma unroll
    for (int i = 0; i < 8; ++i) {
        int idx = tid + i * NTHREADS;     // 1024 chunks (64 rows x 16)
        int r = idx >> 4, c16 = idx & 15;
        const float* src = gq + (size_t)(qbase + r) * (NH * HD) + head * HD + c16 * 8;
        uint32_t h[4];
        #pragma unroll
        for (int e = 0; e < 4; ++e)
            h[e] = packh(__float2half_rn(src[2 * e] * SCALE2),
                         __float2half_rn(src[2 * e + 1] * SCALE2));
        *reinterpret_cast<uint4*>(smem + QH_OFF + sw(r, c16)) = make_uint4(h[0], h[1], h[2], h[3]);
    }
    __syncthreads();   // Q visible to all warps before fragment hoist

    // per-lane constants
    const uint32_t aRowByte = (uint32_t)((warp * 16 + (lane & 15)) * 256);
    const uint32_t aXor = (uint32_t)(lane & 7);
    const uint32_t aC0  = (uint32_t)(lane >> 4);
    const uint32_t kRow8  = (uint32_t)((lane & 7) * 256);
    const uint32_t kHalf  = (uint32_t)((lane >> 3) & 1);
    const uint32_t kJplus = (uint32_t)(lane >> 4);
    const uint32_t kXor   = (uint32_t)(lane & 7);
    const uint32_t vRow16 = (uint32_t)((lane & 15) * 256);
    const uint32_t vJplus = (uint32_t)(lane >> 4);
    const uint32_t vXor   = (uint32_t)(lane & 7);

    // ---- hoist Q fragments into registers; reused for all tiles ----
    uint32_t qh[8][4];
    #pragma unroll
    for (int ks = 0; ks < 8; ++ks) {
        uint32_t aoff = aRowByte + ((((uint32_t)(2 * ks) + aC0) ^ aXor) << 4);
        ldsm4(qh[ks], sb + QH_OFF + aoff);
    }

    const int row0 = qbase + warp * 16 + (lane >> 2);
    const int row1 = row0 + 8;
    const int wrow_min = qbase + warp * 16;        // smallest q row in this warp
    const int wrow_max = wrow_min + 15;            // largest q row in this warp

    float oacc[16][4];
    #pragma unroll
    for (int j = 0; j < 16; ++j)
        #pragma unroll
        for (int e = 0; e < 4; ++e) oacc[j][e] = 0.0f;
    float lsum0 = 0.0f, lsum1 = 0.0f;

    for (int t = 0; t < ntiles; ++t) {
        const int kbase = t * BN;
        const uint32_t stg = sb + STG_OFF + (uint32_t)(t & 1) * STG_SZ;

        CP_WAIT0();
        __syncthreads();   // single barrier: stage t ready AND prior reads of the
                           // other buffer are complete across the CTA

        if (t + 1 < ntiles) {
            load_kv(sb + STG_OFF + (uint32_t)((t + 1) & 1) * STG_SZ,
                    (t + 1) * BN, kvh, tid);
            CP_COMMIT();
        }

        const uint32_t stgKh = stg;
        const uint32_t stgVh = stg + 16384;

        if (kbase + BN - 1 <= wrow_min) {
            // ======== HOT PATH: fully unmasked tile ========
            float sacc[8][4];
            #pragma unroll
            for (int jj = 0; jj < 8; ++jj)
                #pragma unroll
                for (int e = 0; e < 4; ++e) sacc[jj][e] = 0.0f;

            #pragma unroll
            for (int ks = 0; ks < 8; ++ks) {
                uint32_t koff = (((uint32_t)(2 * ks) + kHalf) ^ kXor) << 4;
                #pragma unroll
                for (int g = 0; g < 4; ++g) {   // 4 groups of 16 keys
                    uint32_t kb[4];
                    ldsm4(kb, stgKh + ((uint32_t)(2 * g) + kJplus) * 2048 + kRow8 + koff);
                    mma16816(sacc[2 * g],     qh[ks], kb);
                    mma16816(sacc[2 * g + 1], qh[ks], kb + 2);
                }
            }

            #pragma unroll
            for (int c = 0; c < 2; ++c) {
                float p[4][4];
                #pragma unroll
                for (int jj = 0; jj < 4; ++jj)
                    #pragma unroll
                    for (int e = 0; e < 4; ++e) p[jj][e] = ex2(sacc[4 * c + jj][e]);
                #pragma unroll
                for (int jj = 0; jj < 4; ++jj) {
                    lsum0 += p[jj][0] + p[jj][1];
                    lsum1 += p[jj][2] + p[jj][3];
                }
                uint32_t af[2][4];
                #pragma unroll
                for (int kf = 0; kf < 2; ++kf) {
                    af[kf][0] = packh(__float2half_rn(p[2 * kf][0]),     __float2half_rn(p[2 * kf][1]));
                    af[kf][1] = packh(__float2half_rn(p[2 * kf][2]),     __float2half_rn(p[2 * kf][3]));
                    af[kf][2] = packh(__float2half_rn(p[2 * kf + 1][0]), __float2half_rn(p[2 * kf + 1][1]));
                    af[kf][3] = packh(__float2half_rn(p[2 * kf + 1][2]), __float2half_rn(p[2 * kf + 1][3]));
                }
                #pragma unroll
                for (int kf = 0; kf < 2; ++kf) {
                    const uint32_t vcb = stgVh + (uint32_t)(2 * c + kf) * 4096 + vRow16;
                    #pragma unroll
                    for (int jp = 0; jp < 8; ++jp) {
                        uint32_t vb[4];
                        ldsm4t(vb, vcb + ((((uint32_t)(2 * jp) + vJplus) ^ vXor) << 4));
                        mma16816(oacc[2 * jp],     af[kf], vb);
                        mma16816(oacc[2 * jp + 1], af[kf], vb + 2);
                    }
                }
            }
        } else if (kbase <= wrow_max) {
            // ======== DIAGONAL PATH: chunked with masking ========
            #pragma unroll
            for (int c = 0; c < 2; ++c) {
                const int cb = kbase + 32 * c;
                if (cb > wrow_max) break;

                float sacc[4][4];
                #pragma unroll
                for (int jj = 0; jj < 4; ++jj)
                    #pragma unroll
                    for (int e = 0; e < 4; ++e) sacc[jj][e] = 0.0f;

                const uint32_t kc0 = stgKh + (uint32_t)(4 * c + kJplus) * 2048 + kRow8;
                const uint32_t kc1 = kc0 + 2 * 2048;
                #pragma unroll
                for (int ks = 0; ks < 8; ++ks) {
                    uint32_t kba[4], kbb[4];
                    uint32_t koff = (((uint32_t)(2 * ks) + kHalf) ^ kXor) << 4;
                    ldsm4(kba, kc0 + koff);
                    ldsm4(kbb, kc1 + koff);
                    mma16816(sacc[0], qh[ks], kba);
                    mma16816(sacc[1], qh[ks], kba + 2);
                    mma16816(sacc[2], qh[ks], kbb);
                    mma16816(sacc[3], qh[ks], kbb + 2);
                }

                float p[4][4];
                #pragma unroll
                for (int jj = 0; jj < 4; ++jj) {
                    int col = cb + 8 * jj + 2 * (lane & 3);
                    p[jj][0] = (col     <= row0) ? ex2(sacc[jj][0]) : 0.0f;
                    p[jj][1] = (col + 1 <= row0) ? ex2(sacc[jj][1]) : 0.0f;
                    p[jj][2] = (col     <= row1) ? ex2(sacc[jj][2]) : 0.0f;
                    p[jj][3] = (col + 1 <= row1) ? ex2(sacc[jj][3]) : 0.0f;
                }
                #pragma unroll
                for (int jj = 0; jj < 4; ++jj) {
                    lsum0 += p[jj][0] + p[jj][1];
                    lsum1 += p[jj][2] + p[jj][3];
                }
                uint32_t af[2][4];
                #pragma unroll
                for (int kf = 0; kf < 2; ++kf) {
                    af[kf][0] = packh(__float2half_rn(p[2 * kf][0]),     __float2half_rn(p[2 * kf][1]));
                    af[kf][1] = packh(__float2half_rn(p[2 * kf][2]),     __float2half_rn(p[2 * kf][3]));
                    af[kf][2] = packh(__float2half_rn(p[2 * kf + 1][0]), __float2half_rn(p[2 * kf + 1][1]));
                    af[kf][3] = packh(__float2half_rn(p[2 * kf + 1][2]), __float2half_rn(p[2 * kf + 1][3]));
                }
                #pragma unroll
                for (int kf = 0; kf < 2; ++kf) {
                    const uint32_t vcb = stgVh + (uint32_t)(2 * c + kf) * 4096 + vRow16;
                    #pragma unroll
                    for (int jp = 0; jp < 8; ++jp) {
                        uint32_t vb[4];
                        ldsm4t(vb, vcb + ((((uint32_t)(2 * jp) + vJplus) ^ vXor) << 4));
                        mma16816(oacc[2 * jp],     af[kf], vb);
                        mma16816(oacc[2 * jp + 1], af[kf], vb + 2);
                    }
                }
            }
        }
    }

    // ---- epilogue: reduce l, normalize, store ----
    lsum0 += __shfl_xor_sync(0xffffffffu, lsum0, 1);
    lsum0 += __shfl_xor_sync(0xffffffffu, lsum0, 2);
    lsum1 += __shfl_xor_sync(0xffffffffu, lsum1, 1);
    lsum1 += __shfl_xor_sync(0xffffffffu, lsum1, 2);
    const float inv0 = 1.0f / lsum0;
    const float inv1 = 1.0f / lsum1;

    float* out0 = gout + (size_t)row0 * (NH * HD) + head * HD + 2 * (lane & 3);
    float* out1 = gout + (size_t)row1 * (NH * HD) + head * HD + 2 * (lane & 3);
    #pragma unroll
    for (int j = 0; j < 16; ++j) {
        float2 a = make_float2(oacc[j][0] * inv0, oacc[j][1] * inv0);
        float2 b = make_float2(oacc[j][2] * inv1, oacc[j][3] * inv1);
        *reinterpret_cast<float2*>(out0 + 8 * j) = a;
        *reinterpret_cast<float2*>(out1 + 8 * j) = b;
    }
}

// ---------------- launch ----------------
extern "C" void kernel_launch(void* const* d_in, const int* in_sizes, int n_in,
                              void* d_out, int out_size)
{
    const float* q = (const float*)d_in[0];
    const float* k = (const float*)d_in[1];
    const float* v = (const float*)d_in[2];
    float* out = (float*)d_out;

    prep_h<<<(SEQ * NKV * HD / 8 + 255) / 256, 256>>>(k, v);

    cudaFuncSetAttribute(fa_mma, cudaFuncAttributeMaxDynamicSharedMemorySize, SMEM_TOTAL);
    fa_mma<<<dim3(NH, SEQ / BM), NTHREADS, SMEM_TOTAL>>>(q, out);
}